// round 5
// baseline (speedup 1.0000x reference)
#include <cuda_runtime.h>
#include <cuda_bf16.h>

typedef unsigned int       u32;
typedef unsigned long long u64;

#define BSZ      64
#define ENC_IN   64
#define ENC_HID  256
#define NNODES   2048
#define GHD      128
#define JTOT     (NNODES * GHD)      // 262144
#define LN_EPS   1e-5f

// ---------------- scratch (device globals: allocation-guard safe) ----------
__device__ float g_h1[BSZ * ENC_HID];                  // [m][k] h1 rows
__device__ float g_buf0[(size_t)BSZ * NNODES * GHD];   // enc / layer input
__device__ float g_buf1[(size_t)BSZ * NNODES * GHD];   // layer-1 output
// Wg transposed [n][k] bf16 hi/lo images, row stride 136 halfs (= 68 u32)
__device__ __align__(16) u32 g_BH[2][GHD * 68];
__device__ __align__(16) u32 g_BL[2][GHD * 68];

extern __shared__ __align__(1024) char dynsm[];

// ---------------- helpers ---------------------------------------------------
__device__ __forceinline__ u32 smem_u32(const void* p) {
    u32 a;
    asm("{ .reg .u64 t; cvta.to.shared.u64 t, %1; cvt.u32.u64 %0, t; }"
        : "=r"(a) : "l"(p));
    return a;
}
__device__ __forceinline__ void ldsm4(u32* r, u32 a) {
    asm volatile("ldmatrix.sync.aligned.m8n8.x4.shared.b16 {%0,%1,%2,%3}, [%4];"
                 : "=r"(r[0]), "=r"(r[1]), "=r"(r[2]), "=r"(r[3]) : "r"(a));
}
__device__ __forceinline__ void ldsm4t(u32* r, u32 a) {
    asm volatile("ldmatrix.sync.aligned.m8n8.x4.trans.shared.b16 {%0,%1,%2,%3}, [%4];"
                 : "=r"(r[0]), "=r"(r[1]), "=r"(r[2]), "=r"(r[3]) : "r"(a));
}
__device__ __forceinline__ void mma16816(float* c, const u32* a, u32 b0, u32 b1) {
    asm volatile(
        "mma.sync.aligned.m16n8k16.row.col.f32.bf16.bf16.f32 "
        "{%0,%1,%2,%3}, {%4,%5,%6,%7}, {%8,%9}, {%0,%1,%2,%3};"
        : "+f"(c[0]), "+f"(c[1]), "+f"(c[2]), "+f"(c[3])
        : "r"(a[0]), "r"(a[1]), "r"(a[2]), "r"(a[3]), "r"(b0), "r"(b1));
}
__device__ __forceinline__ void split2(float a, float b, u32& hi, u32& lo) {
    __nv_bfloat162 h = __floats2bfloat162_rn(a, b);
    float ha = __bfloat162float(h.x), hb = __bfloat162float(h.y);
    __nv_bfloat162 l = __floats2bfloat162_rn(a - ha, b - hb);
    hi = *reinterpret_cast<u32*>(&h);
    lo = *reinterpret_cast<u32*>(&l);
}

// ===========================================================================
// K0: Wg -> transposed [n][k] bf16 hi/lo images (stride 136 halfs)
// ===========================================================================
__global__ void k_prep(const float* __restrict__ Wg1, const float* __restrict__ Wg2) {
    const int L = blockIdx.x;
    const float* Wg = L ? Wg2 : Wg1;
    const int n = threadIdx.x;   // 0..127
    for (int k = 0; k < GHD; k += 2) {
        u32 hi, lo;
        split2(Wg[k * GHD + n], Wg[(k + 1) * GHD + n], hi, lo);
        g_BH[L][n * 68 + (k >> 1)] = hi;
        g_BL[L][n * 68 + (k >> 1)] = lo;
    }
}

// ===========================================================================
// K1: h1 = relu(x @ W1 + b1), row-major [m][k]
// ===========================================================================
__global__ void k_enc1(const float* __restrict__ x,
                       const float* __restrict__ W1,
                       const float* __restrict__ b1) {
    const int b = blockIdx.x;
    const int j = threadIdx.x;
    __shared__ float sx[ENC_IN];
    if (j < ENC_IN) sx[j] = x[b * ENC_IN + j];
    __syncthreads();
    float acc = b1[j];
#pragma unroll
    for (int k = 0; k < ENC_IN; k++)
        acc = fmaf(sx[k], W1[k * ENC_HID + j], acc);
    g_h1[b * ENC_HID + j] = fmaxf(acc, 0.0f);
}

// ===========================================================================
// K2: enc = h1 @ W2 + b2 -> g_buf0.  M=64 N=128, K=256 in 8 k32 panels.
// Per-panel A+B staging: smem 27.6KB, 3 blocks/SM, reg prefetch of A+B.
// ===========================================================================
#define EAB       80                       // A panel row stride bytes (32 k)
#define EBB       272                      // B panel row stride bytes (128 n)
#define E_AHI     0
#define E_ALO     5120
#define E_BHI     10240
#define E_BLO     18944
#define E_SMEM    27648

__global__ __launch_bounds__(256, 3) void k_enc2_mma(const float* __restrict__ W2,
                                                     const float* __restrict__ b2) {
    const int tid = threadIdx.x;
    const int L   = tid & 31;
    const int w   = tid >> 5;
    const int j0  = blockIdx.x * 128;
    const u32 sb  = smem_u32(dynsm);

    const int mw = w & 1, nw = w >> 1;
    const int R0 = mw * 32, N0 = nw * 32;
    const u32 arow = (u32)(L & 15);
    const u32 kcol = (u32)((L >> 4) << 3);
    const u32 brow = (u32)((L & 7) + ((L >> 3) & 1) * 8);
    const u32 bcol = (u32)((L >> 4) << 3);

    float acc[2][4][4];
#pragma unroll
    for (int mt = 0; mt < 2; mt++)
#pragma unroll
        for (int j = 0; j < 4; j++)
#pragma unroll
            for (int c = 0; c < 4; c++) acc[mt][j][c] = 0.0f;

    // prefetch panel 0: A (2 float4/thread), B (4 float4/thread)
    float4 pfA[2], pfB[4];
#pragma unroll
    for (int t = 0; t < 2; t++) {
        int i = tid + t * 256;             // 0..511
        int row = i >> 3, c4 = i & 7;
        pfA[t] = *(const float4*)&g_h1[row * ENC_HID + c4 * 4];
    }
#pragma unroll
    for (int t = 0; t < 4; t++) {
        int i = tid + t * 256;             // 0..1023
        int row = i >> 5, c4 = i & 31;
        pfB[t] = *(const float4*)&W2[(size_t)row * JTOT + j0 + c4 * 4];
    }

    for (int kp = 0; kp < 8; kp++) {
        __syncthreads();                   // smem free (prev MMA done)
        // convert prefetched panels -> smem bf16 hi/lo
#pragma unroll
        for (int t = 0; t < 2; t++) {
            int i = tid + t * 256;
            int row = i >> 3, c4 = i & 7;
            u32 h0, l0, h1, l1;
            split2(pfA[t].x, pfA[t].y, h0, l0);
            split2(pfA[t].z, pfA[t].w, h1, l1);
            *(uint2*)(dynsm + E_AHI + row * EAB + c4 * 8) = make_uint2(h0, h1);
            *(uint2*)(dynsm + E_ALO + row * EAB + c4 * 8) = make_uint2(l0, l1);
        }
#pragma unroll
        for (int t = 0; t < 4; t++) {
            int i = tid + t * 256;
            int row = i >> 5, c4 = i & 31;
            u32 h0, l0, h1, l1;
            split2(pfB[t].x, pfB[t].y, h0, l0);
            split2(pfB[t].z, pfB[t].w, h1, l1);
            *(uint2*)(dynsm + E_BHI + row * EBB + c4 * 8) = make_uint2(h0, h1);
            *(uint2*)(dynsm + E_BLO + row * EBB + c4 * 8) = make_uint2(l0, l1);
        }
        __syncthreads();
        // issue next panel's global loads (hide under MMA)
        if (kp < 7) {
#pragma unroll
            for (int t = 0; t < 2; t++) {
                int i = tid + t * 256;
                int row = i >> 3, c4 = i & 7;
                pfA[t] = *(const float4*)&g_h1[row * ENC_HID + (kp + 1) * 32 + c4 * 4];
            }
#pragma unroll
            for (int t = 0; t < 4; t++) {
                int i = tid + t * 256;
                int row = i >> 5, c4 = i & 31;
                pfB[t] = *(const float4*)&W2[(size_t)((kp + 1) * 32 + row) * JTOT +
                                             j0 + c4 * 4];
            }
        }

#pragma unroll
        for (int p = 0; p < 3; p++) {
            const u32 aOff = (p < 2) ? E_AHI : E_ALO;
            const u32 bOff = (p == 1) ? E_BLO : E_BHI;
#pragma unroll
            for (int ks = 0; ks < 2; ks++) {
                u32 a0[4], a1[4];
                u32 ka = (u32)((ks * 16 + kcol) * 2);
                ldsm4(a0, sb + aOff + (R0 + arow) * EAB + ka);
                ldsm4(a1, sb + aOff + (R0 + 16 + arow) * EAB + ka);
                u32 bf[2][4];
                u32 kb = (u32)((ks * 16 + brow) * EBB);
#pragma unroll
                for (int nt = 0; nt < 2; nt++)
                    ldsm4t(bf[nt], sb + bOff + kb + (N0 + nt * 16 + bcol) * 2);
#pragma unroll
                for (int j = 0; j < 4; j++) {
                    u32 b0 = bf[j >> 1][(j & 1) * 2];
                    u32 b1 = bf[j >> 1][(j & 1) * 2 + 1];
                    mma16816(acc[0][j], a0, b0, b1);
                    mma16816(acc[1][j], a1, b0, b1);
                }
            }
        }
    }

    // ---- epilogue ----
#pragma unroll
    for (int mt = 0; mt < 2; mt++) {
        int m = R0 + mt * 16 + (L >> 2);
#pragma unroll
        for (int j = 0; j < 4; j++) {
            int n = j0 + N0 + j * 8 + (L & 3) * 2;
            float b20 = __ldg(&b2[n]), b21 = __ldg(&b2[n + 1]);
            *(float2*)&g_buf0[(size_t)m * JTOT + n] =
                make_float2(acc[mt][j][0] + b20, acc[mt][j][1] + b21);
            *(float2*)&g_buf0[(size_t)(m + 8) * JTOT + n] =
                make_float2(acc[mt][j][2] + b20, acc[mt][j][3] + b21);
        }
    }
}

// ===========================================================================
// K3/K4: fused GCN layer.  M=64 rows (62 out + halo), N=128 in two halves.
// smem 69.6KB -> 3 blocks/SM.  grid(34,64) block(256).
// ===========================================================================
#define GSB       272                      // A/B row stride bytes (136 halfs)
#define G_AHI     0
#define G_ALO     17408
#define G_RB      34816                    // shared region: B-half staging / C
#define G_RLO     52224
#define G_SMEM    69632
#define SC_STRIDE 68
#define ROWS      64
#define OUTR      62

__global__ __launch_bounds__(256, 3) void k_gcn_mma(const float* __restrict__ Ah,
                                                    const float* __restrict__ gam,
                                                    const float* __restrict__ bet,
                                                    const float* __restrict__ Wout,
                                                    const float* __restrict__ bout,
                                                    float* __restrict__ proj,
                                                    int layer) {
    __shared__ float sAp[ROWS], sAn[ROWS], sProj[ROWS];
    __shared__ float sGam[128], sBet[128], sWo[128];

    const float* in  = layer ? g_buf1 : g_buf0;
    float*       out = g_buf1;

    const int tid = threadIdx.x;
    const int L   = tid & 31;
    const int w   = tid >> 5;
    const int b   = blockIdx.y;
    const int n0  = blockIdx.x * OUTR;
    const u32 sb  = smem_u32(dynsm);

    if (tid < 128) {
        sGam[tid] = gam[tid];
        sBet[tid] = bet[tid];
        sWo[tid]  = layer ? Wout[tid] : 0.0f;
    }
    if (tid < ROWS) {
        sProj[tid] = 0.0f;
        int gi = n0 - 1 + tid;
        sAp[tid] = (gi >= 1 && gi < NNODES) ? Ah[(size_t)gi * NNODES + gi - 1] : 0.0f;
        sAn[tid] = (gi >= 0 && gi < NNODES - 1) ? Ah[(size_t)gi * NNODES + gi + 1] : 0.0f;
    }
    __syncthreads();

    // ---- LN + bf16 split -> A tiles (warp w: rows 8w..8w+7) ----
#pragma unroll 2
    for (int rr = 0; rr < 8; rr++) {
        int r  = w * 8 + rr;
        int gi = min(NNODES - 1, max(0, n0 - 1 + r));
        float4 v = *(const float4*)&in[((size_t)b * NNODES + gi) * GHD + L * 4];
        float s = v.x + v.y + v.z + v.w;
        float q = v.x * v.x + v.y * v.y + v.z * v.z + v.w * v.w;
#pragma unroll
        for (int o = 16; o; o >>= 1) {
            s += __shfl_xor_sync(0xFFFFFFFFu, s, o);
            q += __shfl_xor_sync(0xFFFFFFFFu, q, o);
        }
        float mu   = s * (1.0f / GHD);
        float rstd = rsqrtf(fmaxf(q * (1.0f / GHD) - mu * mu, 0.0f) + LN_EPS);
        int c = L * 4;
        float f0 = (v.x - mu) * rstd * sGam[c + 0] + sBet[c + 0];
        float f1 = (v.y - mu) * rstd * sGam[c + 1] + sBet[c + 1];
        float f2 = (v.z - mu) * rstd * sGam[c + 2] + sBet[c + 2];
        float f3 = (v.w - mu) * rstd * sGam[c + 3] + sBet[c + 3];
        u32 h0, l0, h1, l1;
        split2(f0, f1, h0, l0);
        split2(f2, f3, h1, l1);
        *(uint2*)(dynsm + G_AHI + r * GSB + L * 8) = make_uint2(h0, h1);
        *(uint2*)(dynsm + G_ALO + r * GSB + L * 8) = make_uint2(l0, l1);
    }

    // warp tile: 32M x 16N
    const int mw = w & 1, nwh = w >> 1;
    const int R0 = mw * 32, N0 = nwh * 16;
    const u32 arow = (u32)(L & 15);
    const u32 kcol = (u32)((L >> 4) << 3);
    float* sC = (float*)(dynsm + G_RB);

    for (int h = 0; h < 2; h++) {
        if (h) __syncthreads();            // aggregate of prev half done
        // ---- stage B half (linear copy from prepped image) ----
        {
            uint4* dh = (uint4*)(dynsm + G_RB);
            uint4* dl = (uint4*)(dynsm + G_RLO);
            const uint4* shp = (const uint4*)(g_BH[layer] + h * 64 * 68);
            const uint4* slp = (const uint4*)(g_BL[layer] + h * 64 * 68);
            for (int i = tid; i < 1088; i += 256) {
                dh[i] = shp[i];
                dl[i] = slp[i];
            }
        }
        __syncthreads();

        // ---- MMA: 64M x 64N, 3 passes ----
        float acc[2][2][4];
#pragma unroll
        for (int mt = 0; mt < 2; mt++)
#pragma unroll
            for (int j = 0; j < 2; j++)
#pragma unroll
                for (int c = 0; c < 4; c++) acc[mt][j][c] = 0.0f;

#pragma unroll
        for (int p = 0; p < 3; p++) {
            const u32 aOff = (p < 2) ? G_AHI : G_ALO;
            const u32 bOff = (p == 1) ? (u32)G_RLO : (u32)G_RB;
#pragma unroll
            for (int ks = 0; ks < 8; ks++) {
                u32 kb = (u32)((ks * 16 + kcol) * 2);
                u32 a0[4], a1[4];
                ldsm4(a0, sb + aOff + (R0 + arow) * GSB + kb);
                ldsm4(a1, sb + aOff + (R0 + 16 + arow) * GSB + kb);
                u32 bf[4];
                ldsm4(bf, sb + bOff + (N0 + arow) * GSB + kb);
#pragma unroll
                for (int j = 0; j < 2; j++) {
                    u32 b0 = bf[j];
                    u32 b1 = bf[j + 2];
                    mma16816(acc[0][j], a0, b0, b1);
                    mma16816(acc[1][j], a1, b0, b1);
                }
            }
        }
        __syncthreads();                   // B reads done -> reuse region as C

        // ---- C frags -> sC (64 cols of this half) ----
#pragma unroll
        for (int mt = 0; mt < 2; mt++) {
            int m = R0 + mt * 16 + (L >> 2);
#pragma unroll
            for (int j = 0; j < 2; j++) {
                int n = N0 + j * 8 + (L & 3) * 2;
                *(float2*)&sC[m * SC_STRIDE + n] =
                    make_float2(acc[mt][j][0], acc[mt][j][1]);
                *(float2*)&sC[(m + 8) * SC_STRIDE + n] =
                    make_float2(acc[mt][j][2], acc[mt][j][3]);
            }
        }
        __syncthreads();

        // ---- aggregate this half's 64 cols ----
        const int cg = h * 64 + L * 2;     // global col, lane covers 2
        for (int r = 1 + w; r <= OUTR; r += 8) {
            int gi = n0 + r - 1;
            if (gi >= NNODES) continue;
            float2 iv = *(const float2*)&in[((size_t)b * NNODES + gi) * GHD + cg];
            float2 wp = *(const float2*)&sC[(r - 1) * SC_STRIDE + L * 2];
            float2 wn = *(const float2*)&sC[(r + 1) * SC_STRIDE + L * 2];
            float ap = sAp[r], an = sAn[r];
            float2 o;
            o.x = fmaf(an, wn.x, fmaf(ap, wp.x, iv.x));
            o.y = fmaf(an, wn.y, fmaf(ap, wp.y, iv.y));
            if (!layer) {
                *(float2*)&out[((size_t)b * NNODES + gi) * GHD + cg] = o;
            } else {
                float s = o.x * sWo[cg] + o.y * sWo[cg + 1];
#pragma unroll
                for (int off = 16; off; off >>= 1)
                    s += __shfl_xor_sync(0xFFFFFFFFu, s, off);
                if (L == 0) {
                    if (h == 0) sProj[r] = s;
                    else        proj[b * NNODES + gi] = sProj[r] + s + bout[0];
                }
            }
        }
    }
}

// ===========================================================================
extern "C" void kernel_launch(void* const* d_in, const int* in_sizes, int n_in,
                              void* d_out, int out_size) {
    const float* x    = (const float*)d_in[0];
    const float* Ah   = (const float*)d_in[1];
    const float* W1   = (const float*)d_in[2];
    const float* b1   = (const float*)d_in[3];
    const float* W2   = (const float*)d_in[4];
    const float* b2   = (const float*)d_in[5];
    const float* Wg1  = (const float*)d_in[6];
    const float* Wg2  = (const float*)d_in[7];
    const float* g1   = (const float*)d_in[8];
    const float* bb1  = (const float*)d_in[9];
    const float* g2   = (const float*)d_in[10];
    const float* bb2  = (const float*)d_in[11];
    const float* Wout = (const float*)d_in[12];
    const float* bout = (const float*)d_in[13];
    float* out = (float*)d_out;

    cudaFuncSetAttribute(k_enc2_mma, cudaFuncAttributeMaxDynamicSharedMemorySize,
                         E_SMEM);
    cudaFuncSetAttribute(k_gcn_mma, cudaFuncAttributeMaxDynamicSharedMemorySize,
                         G_SMEM);

    k_prep<<<2, GHD>>>(Wg1, Wg2);
    k_enc1<<<BSZ, ENC_HID>>>(x, W1, b1);
    k_enc2_mma<<<JTOT / 128, 256, E_SMEM>>>(W2, b2);
    dim3 gcn_grid((NNODES + OUTR - 1) / OUTR, BSZ);
    k_gcn_mma<<<gcn_grid, 256, G_SMEM>>>(Ah, g1, bb1, Wout, bout, out, 0);
    k_gcn_mma<<<gcn_grid, 256, G_SMEM>>>(Ah, g2, bb2, Wout, bout, out, 1);
}

// round 6
// speedup vs baseline: 1.1038x; 1.1038x over previous
#include <cuda_runtime.h>
#include <cuda_bf16.h>

typedef unsigned int       u32;
typedef unsigned long long u64;

#define BSZ      64
#define ENC_IN   64
#define ENC_HID  256
#define NNODES   2048
#define GHD      128
#define JTOT     (NNODES * GHD)      // 262144
#define LN_EPS   1e-5f

// ---------------- scratch (device globals: allocation-guard safe) ----------
__device__ float g_h1[BSZ * ENC_HID];                  // [m][k] h1 rows
__device__ float g_buf0[(size_t)BSZ * NNODES * GHD];   // enc output
// Wg transposed [n][k] bf16 hi/lo images, row stride 136 halfs (= 68 u32)
__device__ __align__(16) u32 g_BH[2][GHD * 68];
__device__ __align__(16) u32 g_BL[2][GHD * 68];

extern __shared__ __align__(1024) char dynsm[];

// ---------------- helpers ---------------------------------------------------
__device__ __forceinline__ u32 smem_u32(const void* p) {
    u32 a;
    asm("{ .reg .u64 t; cvta.to.shared.u64 t, %1; cvt.u32.u64 %0, t; }"
        : "=r"(a) : "l"(p));
    return a;
}
__device__ __forceinline__ void ldsm4(u32* r, u32 a) {
    asm volatile("ldmatrix.sync.aligned.m8n8.x4.shared.b16 {%0,%1,%2,%3}, [%4];"
                 : "=r"(r[0]), "=r"(r[1]), "=r"(r[2]), "=r"(r[3]) : "r"(a));
}
__device__ __forceinline__ void ldsm4t(u32* r, u32 a) {
    asm volatile("ldmatrix.sync.aligned.m8n8.x4.trans.shared.b16 {%0,%1,%2,%3}, [%4];"
                 : "=r"(r[0]), "=r"(r[1]), "=r"(r[2]), "=r"(r[3]) : "r"(a));
}
__device__ __forceinline__ void mma16816(float* c, const u32* a, u32 b0, u32 b1) {
    asm volatile(
        "mma.sync.aligned.m16n8k16.row.col.f32.bf16.bf16.f32 "
        "{%0,%1,%2,%3}, {%4,%5,%6,%7}, {%8,%9}, {%0,%1,%2,%3};"
        : "+f"(c[0]), "+f"(c[1]), "+f"(c[2]), "+f"(c[3])
        : "r"(a[0]), "r"(a[1]), "r"(a[2]), "r"(a[3]), "r"(b0), "r"(b1));
}
__device__ __forceinline__ void split2(float a, float b, u32& hi, u32& lo) {
    __nv_bfloat162 h = __floats2bfloat162_rn(a, b);
    float ha = __bfloat162float(h.x), hb = __bfloat162float(h.y);
    __nv_bfloat162 l = __floats2bfloat162_rn(a - ha, b - hb);
    hi = *reinterpret_cast<u32*>(&h);
    lo = *reinterpret_cast<u32*>(&l);
}

// ===========================================================================
// K0: Wg -> transposed [n][k] bf16 hi/lo images (stride 136 halfs)
// ===========================================================================
__global__ void k_prep(const float* __restrict__ Wg1, const float* __restrict__ Wg2) {
    const int L = blockIdx.x;
    const float* Wg = L ? Wg2 : Wg1;
    const int n = threadIdx.x;   // 0..127
    for (int k = 0; k < GHD; k += 2) {
        u32 hi, lo;
        split2(Wg[k * GHD + n], Wg[(k + 1) * GHD + n], hi, lo);
        g_BH[L][n * 68 + (k >> 1)] = hi;
        g_BL[L][n * 68 + (k >> 1)] = lo;
    }
}

// ===========================================================================
// K1: h1 = relu(x @ W1 + b1), row-major [m][k]
// ===========================================================================
__global__ void k_enc1(const float* __restrict__ x,
                       const float* __restrict__ W1,
                       const float* __restrict__ b1) {
    const int b = blockIdx.x;
    const int j = threadIdx.x;
    __shared__ float sx[ENC_IN];
    if (j < ENC_IN) sx[j] = x[b * ENC_IN + j];
    __syncthreads();
    float acc = b1[j];
#pragma unroll
    for (int k = 0; k < ENC_IN; k++)
        acc = fmaf(sx[k], W1[k * ENC_HID + j], acc);
    g_h1[b * ENC_HID + j] = fmaxf(acc, 0.0f);
}

// ===========================================================================
// K2: enc = h1 @ W2 + b2 -> g_buf0.  M=64 N=128, K=256 in 8 k32 panels.
// (R4 config: A staged full-K once; B per-panel with register prefetch.)
// ===========================================================================
#define ESB       528
#define EBB       272
#define E_AHI     0
#define E_ALO     33792
#define E_BHI     67584
#define E_BLO     76288
#define E_SMEM    84992

__global__ __launch_bounds__(256, 2) void k_enc2_mma(const float* __restrict__ W2,
                                                     const float* __restrict__ b2) {
    const int tid = threadIdx.x;
    const int L   = tid & 31;
    const int w   = tid >> 5;
    const int j0  = blockIdx.x * 128;
    const u32 sb  = smem_u32(dynsm);

    // ---- stage A = h1 (bf16 hi/lo), full K=256 ----
    for (int i = tid; i < 4096; i += 256) {
        int row = i >> 6, c4 = i & 63;
        float4 v = *(const float4*)&g_h1[row * ENC_HID + c4 * 4];
        u32 h0, l0, h1, l1;
        split2(v.x, v.y, h0, l0);
        split2(v.z, v.w, h1, l1);
        *(uint2*)(dynsm + E_AHI + row * ESB + c4 * 8) = make_uint2(h0, h1);
        *(uint2*)(dynsm + E_ALO + row * ESB + c4 * 8) = make_uint2(l0, l1);
    }

    const int mw = w & 1, nw = w >> 1;
    const int R0 = mw * 32, N0 = nw * 32;
    const u32 arow = (u32)(L & 15);
    const u32 kcol = (u32)((L >> 4) << 3);
    const u32 brow = (u32)((L & 7) + ((L >> 3) & 1) * 8);
    const u32 bcol = (u32)((L >> 4) << 3);

    float acc[2][4][4];
#pragma unroll
    for (int mt = 0; mt < 2; mt++)
#pragma unroll
        for (int j = 0; j < 4; j++)
#pragma unroll
            for (int c = 0; c < 4; c++) acc[mt][j][c] = 0.0f;

    // prefetch B panel 0 (4 float4/thread: 32x128 floats)
    float4 pf[4];
#pragma unroll
    for (int t = 0; t < 4; t++) {
        int i = tid + t * 256;
        int row = i >> 5, c4 = i & 31;
        pf[t] = *(const float4*)&W2[(size_t)row * JTOT + j0 + c4 * 4];
    }

    for (int kp = 0; kp < 8; kp++) {
        __syncthreads();
#pragma unroll
        for (int t = 0; t < 4; t++) {
            int i = tid + t * 256;
            int row = i >> 5, c4 = i & 31;
            u32 h0, l0, h1, l1;
            split2(pf[t].x, pf[t].y, h0, l0);
            split2(pf[t].z, pf[t].w, h1, l1);
            *(uint2*)(dynsm + E_BHI + row * EBB + c4 * 8) = make_uint2(h0, h1);
            *(uint2*)(dynsm + E_BLO + row * EBB + c4 * 8) = make_uint2(l0, l1);
        }
        __syncthreads();
        if (kp < 7) {
#pragma unroll
            for (int t = 0; t < 4; t++) {
                int i = tid + t * 256;
                int row = i >> 5, c4 = i & 31;
                pf[t] = *(const float4*)&W2[(size_t)((kp + 1) * 32 + row) * JTOT +
                                            j0 + c4 * 4];
            }
        }

#pragma unroll
        for (int p = 0; p < 3; p++) {
            const u32 aOff = (p < 2) ? E_AHI : E_ALO;
            const u32 bOff = (p == 1) ? E_BLO : E_BHI;
#pragma unroll
            for (int ks = 0; ks < 2; ks++) {
                u32 a0[4], a1[4];
                u32 ka = (u32)((kp * 32 + ks * 16 + kcol) * 2);
                ldsm4(a0, sb + aOff + (R0 + arow) * ESB + ka);
                ldsm4(a1, sb + aOff + (R0 + 16 + arow) * ESB + ka);
                u32 bf[2][4];
                u32 kb = (u32)((ks * 16 + brow) * EBB);
#pragma unroll
                for (int nt = 0; nt < 2; nt++)
                    ldsm4t(bf[nt], sb + bOff + kb + (N0 + nt * 16 + bcol) * 2);
#pragma unroll
                for (int j = 0; j < 4; j++) {
                    u32 b0 = bf[j >> 1][(j & 1) * 2];
                    u32 b1 = bf[j >> 1][(j & 1) * 2 + 1];
                    mma16816(acc[0][j], a0, b0, b1);
                    mma16816(acc[1][j], a1, b0, b1);
                }
            }
        }
    }

#pragma unroll
    for (int mt = 0; mt < 2; mt++) {
        int m = R0 + mt * 16 + (L >> 2);
#pragma unroll
        for (int j = 0; j < 4; j++) {
            int n = j0 + N0 + j * 8 + (L & 3) * 2;
            float b20 = __ldg(&b2[n]), b21 = __ldg(&b2[n + 1]);
            *(float2*)&g_buf0[(size_t)m * JTOT + n] =
                make_float2(acc[mt][j][0] + b20, acc[mt][j][1] + b21);
            *(float2*)&g_buf0[(size_t)(m + 8) * JTOT + n] =
                make_float2(acc[mt][j][2] + b20, acc[mt][j][3] + b21);
        }
    }
}

// ===========================================================================
// K3: FUSED double GCN layer + output projection.
// Stage 128 rows (halo 2 each side, 124 outputs). Residual rows live in
// registers: warp w owns rows {w+8t}, lane L owns cols {2L,2L+1,64+2L,65+2L}.
// Per layer: LN+split -> A tiles; N in two 64-col halves: stage Bh, MMA
// (3-pass bf16 split), C->smem, aggregate into registers.
// Layer 2 fuses the Wout projection.  grid(17,64) block(256), smem 102KB.
// ===========================================================================
#define GSB       272
#define G_AHI     0
#define G_ALO     34816
#define G_RB      69632                    // B-half hi staging / C tile
#define G_RLO     87040                    // B-half lo staging
#define G_SMEM    104448

__global__ __launch_bounds__(256, 2) void k_gcn_fused(const float* __restrict__ Ah,
                                                      const float* __restrict__ g1,
                                                      const float* __restrict__ bb1,
                                                      const float* __restrict__ g2,
                                                      const float* __restrict__ bb2,
                                                      const float* __restrict__ Wout,
                                                      const float* __restrict__ bout,
                                                      float* __restrict__ proj) {
    __shared__ float sAp[128], sAn[128], sProj[128];
    __shared__ float sG1[128], sB1[128], sG2[128], sB2[128], sWo[128];

    const int tid = threadIdx.x;
    const int L   = tid & 31;
    const int w   = tid >> 5;
    const int b   = blockIdx.y;
    const int n0  = blockIdx.x * 124;      // staged row r <-> gi = n0 - 2 + r
    const u32 sb  = smem_u32(dynsm);

    if (tid < 128) {
        sG1[tid] = g1[tid];
        sB1[tid] = bb1[tid];
        sG2[tid] = g2[tid];
        sB2[tid] = bb2[tid];
        sWo[tid] = Wout[tid];
        int gi = n0 - 2 + tid;
        sAp[tid] = (gi >= 1 && gi < NNODES) ? Ah[(size_t)gi * NNODES + gi - 1] : 0.0f;
        sAn[tid] = (gi >= 0 && gi < NNODES - 1) ? Ah[(size_t)gi * NNODES + gi + 1] : 0.0f;
    }

    // ---- residual registers: 16 rows x 4 cols per thread ----
    float rv[16][4];
#pragma unroll
    for (int t = 0; t < 16; t++) {
        int row = w + 8 * t;
        int gi  = min(NNODES - 1, max(0, n0 - 2 + row));
        const float* p = &g_buf0[((size_t)b * NNODES + gi) * GHD + 2 * L];
        float2 v0 = *(const float2*)p;
        float2 v1 = *(const float2*)(p + 64);
        rv[t][0] = v0.x; rv[t][1] = v0.y; rv[t][2] = v1.x; rv[t][3] = v1.y;
    }
    __syncthreads();

    const int mw = w & 3, nh = w >> 2;
    const int R0 = mw * 32, N0 = nh * 32;
    const u32 arow = (u32)(L & 15);
    const u32 kcol = (u32)((L >> 4) << 3);
    float* sC = (float*)(dynsm + G_RB);
    const int c0 = 2 * L, c2 = 64 + 2 * L;

    for (int layer = 0; layer < 2; layer++) {
        const float* sG = layer ? sG2 : sG1;
        const float* sB = layer ? sB2 : sB1;

        // ---- LN + bf16 split -> A tiles (rows owned by this warp) ----
#pragma unroll
        for (int t = 0; t < 16; t++) {
            int row = w + 8 * t;
            float v0 = rv[t][0], v1 = rv[t][1], v2 = rv[t][2], v3 = rv[t][3];
            float s = v0 + v1 + v2 + v3;
            float q = v0 * v0 + v1 * v1 + v2 * v2 + v3 * v3;
#pragma unroll
            for (int o = 16; o; o >>= 1) {
                s += __shfl_xor_sync(0xFFFFFFFFu, s, o);
                q += __shfl_xor_sync(0xFFFFFFFFu, q, o);
            }
            float mu   = s * (1.0f / GHD);
            float rstd = rsqrtf(fmaxf(q * (1.0f / GHD) - mu * mu, 0.0f) + LN_EPS);
            float f0 = (v0 - mu) * rstd * sG[c0] + sB[c0];
            float f1 = (v1 - mu) * rstd * sG[c0 + 1] + sB[c0 + 1];
            float f2 = (v2 - mu) * rstd * sG[c2] + sB[c2];
            float f3 = (v3 - mu) * rstd * sG[c2 + 1] + sB[c2 + 1];
            u32 h0, l0, h1, l1;
            split2(f0, f1, h0, l0);
            split2(f2, f3, h1, l1);
            *(u32*)(dynsm + G_AHI + row * GSB + L * 4)       = h0;
            *(u32*)(dynsm + G_AHI + row * GSB + 128 + L * 4) = h1;
            *(u32*)(dynsm + G_ALO + row * GSB + L * 4)       = l0;
            *(u32*)(dynsm + G_ALO + row * GSB + 128 + L * 4) = l1;
        }
        __syncthreads();

        for (int h = 0; h < 2; h++) {
            // ---- stage B half (linear copy from prepped image) ----
            {
                uint4* dh = (uint4*)(dynsm + G_RB);
                uint4* dl = (uint4*)(dynsm + G_RLO);
                const uint4* shp = (const uint4*)(g_BH[layer] + h * 64 * 68);
                const uint4* slp = (const uint4*)(g_BL[layer] + h * 64 * 68);
                for (int i = tid; i < 1088; i += 256) {
                    dh[i] = shp[i];
                    dl[i] = slp[i];
                }
            }
            __syncthreads();

            // ---- MMA: 128M x 64N, 3 passes (warp tile 32x32) ----
            float acc[2][4][4];
#pragma unroll
            for (int mt = 0; mt < 2; mt++)
#pragma unroll
                for (int j = 0; j < 4; j++)
#pragma unroll
                    for (int c = 0; c < 4; c++) acc[mt][j][c] = 0.0f;

#pragma unroll
            for (int p = 0; p < 3; p++) {
                const u32 aOff = (p < 2) ? G_AHI : G_ALO;
                const u32 bOff = (p == 1) ? (u32)G_RLO : (u32)G_RB;
#pragma unroll
                for (int ks = 0; ks < 8; ks++) {
                    u32 kb = (u32)((ks * 16 + kcol) * 2);
                    u32 a0[4], a1[4];
                    ldsm4(a0, sb + aOff + (R0 + arow) * GSB + kb);
                    ldsm4(a1, sb + aOff + (R0 + 16 + arow) * GSB + kb);
                    u32 bf[2][4];
#pragma unroll
                    for (int nt = 0; nt < 2; nt++)
                        ldsm4(bf[nt], sb + bOff + (N0 + nt * 16 + arow) * GSB + kb);
#pragma unroll
                    for (int j = 0; j < 4; j++) {
                        u32 b0 = bf[j >> 1][(j & 1)];
                        u32 b1 = bf[j >> 1][(j & 1) + 2];
                        mma16816(acc[0][j], a0, b0, b1);
                        mma16816(acc[1][j], a1, b0, b1);
                    }
                }
            }
            __syncthreads();               // B reads done -> region becomes C

            // ---- C frags -> sC ----
#pragma unroll
            for (int mt = 0; mt < 2; mt++) {
                int m = R0 + mt * 16 + (L >> 2);
#pragma unroll
                for (int j = 0; j < 4; j++) {
                    int n = N0 + j * 8 + (L & 3) * 2;
                    *(float2*)&sC[m * 68 + n] =
                        make_float2(acc[mt][j][0], acc[mt][j][1]);
                    *(float2*)&sC[(m + 8) * 68 + n] =
                        make_float2(acc[mt][j][2], acc[mt][j][3]);
                }
            }
            __syncthreads();

            // ---- aggregate this half's 64 cols into registers ----
            const int jh = h * 2;
            const int lo = layer ? 2 : 1;
            const int hi = layer ? 125 : 126;
#pragma unroll
            for (int t = 0; t < 16; t++) {
                int row = w + 8 * t;
                if (row < lo || row > hi) continue;
                float ap = sAp[row], an = sAn[row];
                float2 wp = *(const float2*)&sC[(row - 1) * 68 + 2 * L];
                float2 wn = *(const float2*)&sC[(row + 1) * 68 + 2 * L];
                float o0 = fmaf(an, wn.x, fmaf(ap, wp.x, rv[t][jh]));
                float o1 = fmaf(an, wn.y, fmaf(ap, wp.y, rv[t][jh + 1]));
                if (!layer) {
                    rv[t][jh]     = o0;
                    rv[t][jh + 1] = o1;
                } else {
                    int cg = h * 64 + 2 * L;
                    float s = o0 * sWo[cg] + o1 * sWo[cg + 1];
#pragma unroll
                    for (int off = 16; off; off >>= 1)
                        s += __shfl_xor_sync(0xFFFFFFFFu, s, off);
                    if (L == 0) {
                        if (h == 0) {
                            sProj[row] = s;
                        } else {
                            int gi = n0 - 2 + row;
                            if (gi < NNODES)
                                proj[b * NNODES + gi] = sProj[row] + s + bout[0];
                        }
                    }
                }
            }
            __syncthreads();               // sC reads done before next staging
        }
    }
}

// ===========================================================================
extern "C" void kernel_launch(void* const* d_in, const int* in_sizes, int n_in,
                              void* d_out, int out_size) {
    const float* x    = (const float*)d_in[0];
    const float* Ah   = (const float*)d_in[1];
    const float* W1   = (const float*)d_in[2];
    const float* b1   = (const float*)d_in[3];
    const float* W2   = (const float*)d_in[4];
    const float* b2   = (const float*)d_in[5];
    const float* Wg1  = (const float*)d_in[6];
    const float* Wg2  = (const float*)d_in[7];
    const float* g1   = (const float*)d_in[8];
    const float* bb1  = (const float*)d_in[9];
    const float* g2   = (const float*)d_in[10];
    const float* bb2  = (const float*)d_in[11];
    const float* Wout = (const float*)d_in[12];
    const float* bout = (const float*)d_in[13];
    float* out = (float*)d_out;

    cudaFuncSetAttribute(k_enc2_mma, cudaFuncAttributeMaxDynamicSharedMemorySize,
                         E_SMEM);
    cudaFuncSetAttribute(k_gcn_fused, cudaFuncAttributeMaxDynamicSharedMemorySize,
                         G_SMEM);

    k_prep<<<2, GHD>>>(Wg1, Wg2);
    k_enc1<<<BSZ, ENC_HID>>>(x, W1, b1);
    k_enc2_mma<<<JTOT / 128, 256, E_SMEM>>>(W2, b2);
    dim3 gcn_grid(17, BSZ);
    k_gcn_fused<<<gcn_grid, 256, G_SMEM>>>(Ah, g1, bb1, g2, bb2, Wout, bout, out);
}

// round 7
// speedup vs baseline: 1.4354x; 1.3004x over previous
#include <cuda_runtime.h>
#include <cuda_bf16.h>

typedef unsigned int       u32;
typedef unsigned long long u64;

#define BSZ      64
#define ENC_IN   64
#define ENC_HID  256
#define NNODES   2048
#define GHD      128
#define JTOT     (NNODES * GHD)      // 262144
#define LN_EPS   1e-5f

// ---------------- scratch (device globals: allocation-guard safe) ----------
__device__ float g_h1[BSZ * ENC_HID];                  // [m][k] h1 rows
__device__ float g_buf0[(size_t)BSZ * NNODES * GHD];   // enc output
// Wg1 transposed [n][k] bf16 hi/lo image, row stride 136 halfs (= 68 u32)
__device__ __align__(16) u32 g_BH[GHD * 68];
__device__ __align__(16) u32 g_BL[GHD * 68];
// layer-2 collapse vectors: w2o = Wg2 @ Wout; gw = g2*w2o; K = {sum(gw), sum(b2*w2o)}
__device__ float g_gw[GHD];
__device__ float g_K[2];

extern __shared__ __align__(1024) char dynsm[];

// ---------------- helpers ---------------------------------------------------
__device__ __forceinline__ u32 smem_u32(const void* p) {
    u32 a;
    asm("{ .reg .u64 t; cvta.to.shared.u64 t, %1; cvt.u32.u64 %0, t; }"
        : "=r"(a) : "l"(p));
    return a;
}
__device__ __forceinline__ void ldsm4(u32* r, u32 a) {
    asm volatile("ldmatrix.sync.aligned.m8n8.x4.shared.b16 {%0,%1,%2,%3}, [%4];"
                 : "=r"(r[0]), "=r"(r[1]), "=r"(r[2]), "=r"(r[3]) : "r"(a));
}
__device__ __forceinline__ void ldsm4t(u32* r, u32 a) {
    asm volatile("ldmatrix.sync.aligned.m8n8.x4.trans.shared.b16 {%0,%1,%2,%3}, [%4];"
                 : "=r"(r[0]), "=r"(r[1]), "=r"(r[2]), "=r"(r[3]) : "r"(a));
}
__device__ __forceinline__ void mma16816(float* c, const u32* a, u32 b0, u32 b1) {
    asm volatile(
        "mma.sync.aligned.m16n8k16.row.col.f32.bf16.bf16.f32 "
        "{%0,%1,%2,%3}, {%4,%5,%6,%7}, {%8,%9}, {%0,%1,%2,%3};"
        : "+f"(c[0]), "+f"(c[1]), "+f"(c[2]), "+f"(c[3])
        : "r"(a[0]), "r"(a[1]), "r"(a[2]), "r"(a[3]), "r"(b0), "r"(b1));
}
__device__ __forceinline__ void split2(float a, float b, u32& hi, u32& lo) {
    __nv_bfloat162 h = __floats2bfloat162_rn(a, b);
    float ha = __bfloat162float(h.x), hb = __bfloat162float(h.y);
    __nv_bfloat162 l = __floats2bfloat162_rn(a - ha, b - hb);
    hi = *reinterpret_cast<u32*>(&h);
    lo = *reinterpret_cast<u32*>(&l);
}

// ===========================================================================
// K0: block 0: Wg1 -> transposed bf16 hi/lo image.
//     block 1: w2o = Wg2 @ Wout; gw = g2*w2o; K = {sum gw, sum b2*w2o}.
// ===========================================================================
__global__ void k_prep(const float* __restrict__ Wg1, const float* __restrict__ Wg2,
                       const float* __restrict__ Wout, const float* __restrict__ g2,
                       const float* __restrict__ b2) {
    const int n = threadIdx.x;   // 0..127
    if (blockIdx.x == 0) {
        for (int k = 0; k < GHD; k += 2) {
            u32 hi, lo;
            split2(Wg1[k * GHD + n], Wg1[(k + 1) * GHD + n], hi, lo);
            g_BH[n * 68 + (k >> 1)] = hi;
            g_BL[n * 68 + (k >> 1)] = lo;
        }
    } else {
        __shared__ float sr1[GHD], sr2[GHD];
        float w2o = 0.0f;
        for (int d = 0; d < GHD; d++)
            w2o = fmaf(Wg2[n * GHD + d], Wout[d], w2o);
        float gwv = g2[n] * w2o;
        g_gw[n] = gwv;
        sr1[n] = gwv;
        sr2[n] = b2[n] * w2o;
        __syncthreads();
        if (n == 0) {
            float k1 = 0.0f, k2 = 0.0f;
            for (int i = 0; i < GHD; i++) { k1 += sr1[i]; k2 += sr2[i]; }
            g_K[0] = k1;
            g_K[1] = k2;
        }
    }
}

// ===========================================================================
// K1: h1 = relu(x @ W1 + b1), row-major [m][k]
// ===========================================================================
__global__ void k_enc1(const float* __restrict__ x,
                       const float* __restrict__ W1,
                       const float* __restrict__ b1) {
    const int b = blockIdx.x;
    const int j = threadIdx.x;
    __shared__ float sx[ENC_IN];
    if (j < ENC_IN) sx[j] = x[b * ENC_IN + j];
    __syncthreads();
    float acc = b1[j];
#pragma unroll
    for (int k = 0; k < ENC_IN; k++)
        acc = fmaf(sx[k], W1[k * ENC_HID + j], acc);
    g_h1[b * ENC_HID + j] = fmaxf(acc, 0.0f);
}

// ===========================================================================
// K2: enc = h1 @ W2 + b2 -> g_buf0.  M=64 N=128, K=256 in 8 k32 panels.
// ===========================================================================
#define ESB       528
#define EBB       272
#define E_AHI     0
#define E_ALO     33792
#define E_BHI     67584
#define E_BLO     76288
#define E_SMEM    84992

__global__ __launch_bounds__(256, 2) void k_enc2_mma(const float* __restrict__ W2,
                                                     const float* __restrict__ b2) {
    const int tid = threadIdx.x;
    const int L   = tid & 31;
    const int w   = tid >> 5;
    const int j0  = blockIdx.x * 128;
    const u32 sb  = smem_u32(dynsm);

    // ---- stage A = h1 (bf16 hi/lo), full K=256 ----
    for (int i = tid; i < 4096; i += 256) {
        int row = i >> 6, c4 = i & 63;
        float4 v = *(const float4*)&g_h1[row * ENC_HID + c4 * 4];
        u32 h0, l0, h1, l1;
        split2(v.x, v.y, h0, l0);
        split2(v.z, v.w, h1, l1);
        *(uint2*)(dynsm + E_AHI + row * ESB + c4 * 8) = make_uint2(h0, h1);
        *(uint2*)(dynsm + E_ALO + row * ESB + c4 * 8) = make_uint2(l0, l1);
    }

    const int mw = w & 1, nw = w >> 1;
    const int R0 = mw * 32, N0 = nw * 32;
    const u32 arow = (u32)(L & 15);
    const u32 kcol = (u32)((L >> 4) << 3);
    const u32 brow = (u32)((L & 7) + ((L >> 3) & 1) * 8);
    const u32 bcol = (u32)((L >> 4) << 3);

    float acc[2][4][4];
#pragma unroll
    for (int mt = 0; mt < 2; mt++)
#pragma unroll
        for (int j = 0; j < 4; j++)
#pragma unroll
            for (int c = 0; c < 4; c++) acc[mt][j][c] = 0.0f;

    float4 pf[4];
#pragma unroll
    for (int t = 0; t < 4; t++) {
        int i = tid + t * 256;
        int row = i >> 5, c4 = i & 31;
        pf[t] = *(const float4*)&W2[(size_t)row * JTOT + j0 + c4 * 4];
    }

    for (int kp = 0; kp < 8; kp++) {
        __syncthreads();
#pragma unroll
        for (int t = 0; t < 4; t++) {
            int i = tid + t * 256;
            int row = i >> 5, c4 = i & 31;
            u32 h0, l0, h1, l1;
            split2(pf[t].x, pf[t].y, h0, l0);
            split2(pf[t].z, pf[t].w, h1, l1);
            *(uint2*)(dynsm + E_BHI + row * EBB + c4 * 8) = make_uint2(h0, h1);
            *(uint2*)(dynsm + E_BLO + row * EBB + c4 * 8) = make_uint2(l0, l1);
        }
        __syncthreads();
        if (kp < 7) {
#pragma unroll
            for (int t = 0; t < 4; t++) {
                int i = tid + t * 256;
                int row = i >> 5, c4 = i & 31;
                pf[t] = *(const float4*)&W2[(size_t)((kp + 1) * 32 + row) * JTOT +
                                            j0 + c4 * 4];
            }
        }

#pragma unroll
        for (int p = 0; p < 3; p++) {
            const u32 aOff = (p < 2) ? E_AHI : E_ALO;
            const u32 bOff = (p == 1) ? E_BLO : E_BHI;
#pragma unroll
            for (int ks = 0; ks < 2; ks++) {
                u32 a0[4], a1[4];
                u32 ka = (u32)((kp * 32 + ks * 16 + kcol) * 2);
                ldsm4(a0, sb + aOff + (R0 + arow) * ESB + ka);
                ldsm4(a1, sb + aOff + (R0 + 16 + arow) * ESB + ka);
                u32 bf[2][4];
                u32 kb = (u32)((ks * 16 + brow) * EBB);
#pragma unroll
                for (int nt = 0; nt < 2; nt++)
                    ldsm4t(bf[nt], sb + bOff + kb + (N0 + nt * 16 + bcol) * 2);
#pragma unroll
                for (int j = 0; j < 4; j++) {
                    u32 b0 = bf[j >> 1][(j & 1) * 2];
                    u32 b1 = bf[j >> 1][(j & 1) * 2 + 1];
                    mma16816(acc[0][j], a0, b0, b1);
                    mma16816(acc[1][j], a1, b0, b1);
                }
            }
        }
    }

#pragma unroll
    for (int mt = 0; mt < 2; mt++) {
        int m = R0 + mt * 16 + (L >> 2);
#pragma unroll
        for (int j = 0; j < 4; j++) {
            int n = j0 + N0 + j * 8 + (L & 3) * 2;
            float b20 = __ldg(&b2[n]), b21 = __ldg(&b2[n + 1]);
            *(float2*)&g_buf0[(size_t)m * JTOT + n] =
                make_float2(acc[mt][j][0] + b20, acc[mt][j][1] + b21);
            *(float2*)&g_buf0[(size_t)(m + 8) * JTOT + n] =
                make_float2(acc[mt][j][2] + b20, acc[mt][j][3] + b21);
        }
    }
}

// ===========================================================================
// K3: fused GCN layer-1 GEMM + collapsed layer-2 + projection.
// Stage 128 rows (124 outputs, halo 2). Layer 1: LN+split -> A, MMA with Wg1
// (3-pass, two 64-col halves), C->smem.  For each row: out1 = enc + chain-agg,
// reduced immediately into 4 dots (sum, sumsq, .Wout, .gw) -> t,u scalars.
// final = t + ap*u_prev + an*u_next + bout.   grid(17,64) block(256).
// ===========================================================================
#define GSB       272
#define G_AHI     0
#define G_ALO     34816
#define G_RB      69632                    // B-half hi staging / C tile
#define G_RLO     87040                    // B-half lo staging
#define G_SMEM    104448

__global__ __launch_bounds__(256, 2) void k_gcn_fused(const float* __restrict__ Ah,
                                                      const float* __restrict__ g1,
                                                      const float* __restrict__ bb1,
                                                      const float* __restrict__ Wout,
                                                      const float* __restrict__ bout,
                                                      float* __restrict__ proj) {
    __shared__ float sAp[128], sAn[128];
    __shared__ float sG1[128], sB1[128], sWo[128], sGw[128];
    __shared__ float sP[128][4];           // per-row partial dots (half 0)
    __shared__ float sT[128], sU[128];

    const int tid = threadIdx.x;
    const int L   = tid & 31;
    const int w   = tid >> 5;
    const int b   = blockIdx.y;
    const int n0  = blockIdx.x * 124;      // staged row r <-> gi = n0 - 2 + r
    const u32 sb  = smem_u32(dynsm);

    if (tid < 128) {
        sG1[tid] = g1[tid];
        sB1[tid] = bb1[tid];
        sWo[tid] = Wout[tid];
        sGw[tid] = g_gw[tid];
        int gi = n0 - 2 + tid;
        sAp[tid] = (gi >= 1 && gi < NNODES) ? Ah[(size_t)gi * NNODES + gi - 1] : 0.0f;
        sAn[tid] = (gi >= 0 && gi < NNODES - 1) ? Ah[(size_t)gi * NNODES + gi + 1] : 0.0f;
    }

    // ---- stage B half 0 (issued early; covered by the sync after LN) ----
    {
        uint4* dh = (uint4*)(dynsm + G_RB);
        uint4* dl = (uint4*)(dynsm + G_RLO);
        for (int i = tid; i < 1088; i += 256) {
            dh[i] = ((const uint4*)g_BH)[i];
            dl[i] = ((const uint4*)g_BL)[i];
        }
    }

    // ---- LN1 + bf16 split -> A tiles (warp w owns rows {w+8t}) ----
    const int c0 = 2 * L, c2 = 64 + 2 * L;
#pragma unroll 4
    for (int t = 0; t < 16; t++) {
        int row = w + 8 * t;
        int gi  = min(NNODES - 1, max(0, n0 - 2 + row));
        const float* p = &g_buf0[((size_t)b * NNODES + gi) * GHD + c0];
        float2 v0 = *(const float2*)p;
        float2 v1 = *(const float2*)(p + 64);
        float s = v0.x + v0.y + v1.x + v1.y;
        float q = v0.x * v0.x + v0.y * v0.y + v1.x * v1.x + v1.y * v1.y;
#pragma unroll
        for (int o = 16; o; o >>= 1) {
            s += __shfl_xor_sync(0xFFFFFFFFu, s, o);
            q += __shfl_xor_sync(0xFFFFFFFFu, q, o);
        }
        float mu   = s * (1.0f / GHD);
        float rstd = rsqrtf(fmaxf(q * (1.0f / GHD) - mu * mu, 0.0f) + LN_EPS);
        float f0 = (v0.x - mu) * rstd * sG1[c0] + sB1[c0];
        float f1 = (v0.y - mu) * rstd * sG1[c0 + 1] + sB1[c0 + 1];
        float f2 = (v1.x - mu) * rstd * sG1[c2] + sB1[c2];
        float f3 = (v1.y - mu) * rstd * sG1[c2 + 1] + sB1[c2 + 1];
        u32 h0, l0, h1, l1;
        split2(f0, f1, h0, l0);
        split2(f2, f3, h1, l1);
        *(u32*)(dynsm + G_AHI + row * GSB + L * 4)       = h0;
        *(u32*)(dynsm + G_AHI + row * GSB + 128 + L * 4) = h1;
        *(u32*)(dynsm + G_ALO + row * GSB + L * 4)       = l0;
        *(u32*)(dynsm + G_ALO + row * GSB + 128 + L * 4) = l1;
    }
    __syncthreads();

    const int mw = w & 3, nh = w >> 2;
    const int R0 = mw * 32, N0 = nh * 32;
    const u32 arow = (u32)(L & 15);
    const u32 kcol = (u32)((L >> 4) << 3);
    float* sC = (float*)(dynsm + G_RB);
    const float K1 = g_K[0], K2 = g_K[1];

    for (int h = 0; h < 2; h++) {
        if (h) {
            // ---- stage B half 1 ----
            uint4* dh = (uint4*)(dynsm + G_RB);
            uint4* dl = (uint4*)(dynsm + G_RLO);
            for (int i = tid; i < 1088; i += 256) {
                dh[i] = ((const uint4*)g_BH)[1088 + i];
                dl[i] = ((const uint4*)g_BL)[1088 + i];
            }
            __syncthreads();
        }

        // ---- MMA: 128M x 64N, 3-pass bf16 split (warp tile 32x32) ----
        float acc[2][4][4];
#pragma unroll
        for (int mt = 0; mt < 2; mt++)
#pragma unroll
            for (int j = 0; j < 4; j++)
#pragma unroll
                for (int c = 0; c < 4; c++) acc[mt][j][c] = 0.0f;

#pragma unroll
        for (int p = 0; p < 3; p++) {
            const u32 aOff = (p < 2) ? G_AHI : G_ALO;
            const u32 bOff = (p == 1) ? (u32)G_RLO : (u32)G_RB;
#pragma unroll
            for (int ks = 0; ks < 8; ks++) {
                u32 kb = (u32)((ks * 16 + kcol) * 2);
                u32 a0[4], a1[4];
                ldsm4(a0, sb + aOff + (R0 + arow) * GSB + kb);
                ldsm4(a1, sb + aOff + (R0 + 16 + arow) * GSB + kb);
                u32 bf[2][4];
#pragma unroll
                for (int nt = 0; nt < 2; nt++)
                    ldsm4(bf[nt], sb + bOff + (N0 + nt * 16 + arow) * GSB + kb);
#pragma unroll
                for (int j = 0; j < 4; j++) {
                    u32 b0 = bf[j >> 1][(j & 1)];
                    u32 b1 = bf[j >> 1][(j & 1) + 2];
                    mma16816(acc[0][j], a0, b0, b1);
                    mma16816(acc[1][j], a1, b0, b1);
                }
            }
        }
        __syncthreads();                   // B reads done -> region becomes C

        // ---- C frags -> sC ----
#pragma unroll
        for (int mt = 0; mt < 2; mt++) {
            int m = R0 + mt * 16 + (L >> 2);
#pragma unroll
            for (int j = 0; j < 4; j++) {
                int n = N0 + j * 8 + (L & 3) * 2;
                *(float2*)&sC[m * 68 + n] =
                    make_float2(acc[mt][j][0], acc[mt][j][1]);
                *(float2*)&sC[(m + 8) * 68 + n] =
                    make_float2(acc[mt][j][2], acc[mt][j][3]);
            }
        }
        __syncthreads();

        // ---- dot pass: out1 cols of this half -> 4 partial dots per row ----
        const int cg = h * 64 + 2 * L;
#pragma unroll 2
        for (int t = 0; t < 16; t++) {
            int row = w + 8 * t;
            if (row < 1 || row > 126) continue;
            int gi = min(NNODES - 1, max(0, n0 - 2 + row));
            float2 iv = *(const float2*)&g_buf0[((size_t)b * NNODES + gi) * GHD + cg];
            float2 wp = *(const float2*)&sC[(row - 1) * 68 + 2 * L];
            float2 wn = *(const float2*)&sC[(row + 1) * 68 + 2 * L];
            float ap = sAp[row], an = sAn[row];
            float o0 = fmaf(an, wn.x, fmaf(ap, wp.x, iv.x));
            float o1 = fmaf(an, wn.y, fmaf(ap, wp.y, iv.y));
            float sv = o0 + o1;
            float sq = o0 * o0 + o1 * o1;
            float st = o0 * sWo[cg] + o1 * sWo[cg + 1];
            float sg = o0 * sGw[cg] + o1 * sGw[cg + 1];
#pragma unroll
            for (int o = 16; o; o >>= 1) {
                sv += __shfl_xor_sync(0xFFFFFFFFu, sv, o);
                sq += __shfl_xor_sync(0xFFFFFFFFu, sq, o);
                st += __shfl_xor_sync(0xFFFFFFFFu, st, o);
                sg += __shfl_xor_sync(0xFFFFFFFFu, sg, o);
            }
            if (L == 0) {
                if (h == 0) {
                    sP[row][0] = sv; sP[row][1] = sq;
                    sP[row][2] = st; sP[row][3] = sg;
                } else {
                    sv += sP[row][0];
                    sq += sP[row][1];
                    st += sP[row][2];
                    sg += sP[row][3];
                    float mu   = sv * (1.0f / GHD);
                    float rstd = rsqrtf(fmaxf(sq * (1.0f / GHD) - mu * mu, 0.0f) +
                                        LN_EPS);
                    sT[row] = st;
                    sU[row] = rstd * (sg - mu * K1) + K2;
                }
            }
        }
        __syncthreads();
    }

    // ---- final: rows 2..125 -> proj ----
    if (tid < 124) {
        int row = tid + 2;
        int gi  = n0 + tid;
        if (gi < NNODES) {
            float f = sT[row] + sAp[row] * sU[row - 1] + sAn[row] * sU[row + 1] +
                      bout[0];
            proj[b * NNODES + gi] = f;
        }
    }
}

// ===========================================================================
extern "C" void kernel_launch(void* const* d_in, const int* in_sizes, int n_in,
                              void* d_out, int out_size) {
    const float* x    = (const float*)d_in[0];
    const float* Ah   = (const float*)d_in[1];
    const float* W1   = (const float*)d_in[2];
    const float* b1   = (const float*)d_in[3];
    const float* W2   = (const float*)d_in[4];
    const float* b2   = (const float*)d_in[5];
    const float* Wg1  = (const float*)d_in[6];
    const float* Wg2  = (const float*)d_in[7];
    const float* g1   = (const float*)d_in[8];
    const float* bb1  = (const float*)d_in[9];
    const float* g2   = (const float*)d_in[10];
    const float* bb2  = (const float*)d_in[11];
    const float* Wout = (const float*)d_in[12];
    const float* bout = (const float*)d_in[13];
    float* out = (float*)d_out;

    cudaFuncSetAttribute(k_enc2_mma, cudaFuncAttributeMaxDynamicSharedMemorySize,
                         E_SMEM);
    cudaFuncSetAttribute(k_gcn_fused, cudaFuncAttributeMaxDynamicSharedMemorySize,
                         G_SMEM);

    k_prep<<<2, GHD>>>(Wg1, Wg2, Wout, g2, bb2);
    k_enc1<<<BSZ, ENC_HID>>>(x, W1, b1);
    k_enc2_mma<<<JTOT / 128, 256, E_SMEM>>>(W2, b2);
    dim3 gcn_grid(17, BSZ);
    k_gcn_fused<<<gcn_grid, 256, G_SMEM>>>(Ah, g1, bb1, Wout, bout, out);
}

// round 8
// speedup vs baseline: 1.4613x; 1.0181x over previous
#include <cuda_runtime.h>
#include <cuda_bf16.h>

typedef unsigned int       u32;
typedef unsigned long long u64;

#define BSZ      64
#define ENC_IN   64
#define ENC_HID  256
#define NNODES   2048
#define GHD      128
#define JTOT     (NNODES * GHD)      // 262144
#define LN_EPS   1e-5f

#define N_ENC_BLK NNODES             // 2048 (one node per enc block)
#define N_GCN_BLK (17 * BSZ)         // 1088

// ---------------- scratch (device globals: allocation-guard safe) ----------
__device__ float g_h1[BSZ * ENC_HID];                  // [m][k] h1 rows
__device__ float g_buf0[(size_t)BSZ * NNODES * GHD];   // enc output
// Wg1 transposed [n][k] bf16 hi/lo image, row stride 136 halfs (= 68 u32)
__device__ __align__(16) u32 g_BH[GHD * 68];
__device__ __align__(16) u32 g_BL[GHD * 68];
// layer-2 collapse vectors: w2o = Wg2 @ Wout; gw = g2*w2o; K = {sum gw, sum b2*w2o}
__device__ float g_gw[GHD];
__device__ float g_K[2];
// per-node completion flags for producer/consumer overlap
__device__ int g_flag[NNODES];

extern __shared__ __align__(1024) char dynsm[];

// ---------------- helpers ---------------------------------------------------
__device__ __forceinline__ u32 smem_u32(const void* p) {
    u32 a;
    asm("{ .reg .u64 t; cvta.to.shared.u64 t, %1; cvt.u32.u64 %0, t; }"
        : "=r"(a) : "l"(p));
    return a;
}
__device__ __forceinline__ void ldsm4(u32* r, u32 a) {
    asm volatile("ldmatrix.sync.aligned.m8n8.x4.shared.b16 {%0,%1,%2,%3}, [%4];"
                 : "=r"(r[0]), "=r"(r[1]), "=r"(r[2]), "=r"(r[3]) : "r"(a));
}
__device__ __forceinline__ void ldsm4t(u32* r, u32 a) {
    asm volatile("ldmatrix.sync.aligned.m8n8.x4.trans.shared.b16 {%0,%1,%2,%3}, [%4];"
                 : "=r"(r[0]), "=r"(r[1]), "=r"(r[2]), "=r"(r[3]) : "r"(a));
}
__device__ __forceinline__ void mma16816(float* c, const u32* a, u32 b0, u32 b1) {
    asm volatile(
        "mma.sync.aligned.m16n8k16.row.col.f32.bf16.bf16.f32 "
        "{%0,%1,%2,%3}, {%4,%5,%6,%7}, {%8,%9}, {%0,%1,%2,%3};"
        : "+f"(c[0]), "+f"(c[1]), "+f"(c[2]), "+f"(c[3])
        : "r"(a[0]), "r"(a[1]), "r"(a[2]), "r"(a[3]), "r"(b0), "r"(b1));
}
__device__ __forceinline__ void split2(float a, float b, u32& hi, u32& lo) {
    __nv_bfloat162 h = __floats2bfloat162_rn(a, b);
    float ha = __bfloat162float(h.x), hb = __bfloat162float(h.y);
    __nv_bfloat162 l = __floats2bfloat162_rn(a - ha, b - hb);
    hi = *reinterpret_cast<u32*>(&h);
    lo = *reinterpret_cast<u32*>(&l);
}

// ===========================================================================
// K0: block 0: Wg1 -> transposed bf16 hi/lo image.
//     block 1: w2o = Wg2 @ Wout; gw = g2*w2o; K = {sum gw, sum b2*w2o}.
// ===========================================================================
__global__ void k_prep(const float* __restrict__ Wg1, const float* __restrict__ Wg2,
                       const float* __restrict__ Wout, const float* __restrict__ g2,
                       const float* __restrict__ b2) {
    const int n = threadIdx.x;   // 0..127
    if (blockIdx.x == 0) {
        for (int k = 0; k < GHD; k += 2) {
            u32 hi, lo;
            split2(Wg1[k * GHD + n], Wg1[(k + 1) * GHD + n], hi, lo);
            g_BH[n * 68 + (k >> 1)] = hi;
            g_BL[n * 68 + (k >> 1)] = lo;
        }
    } else {
        __shared__ float sr1[GHD], sr2[GHD];
        float w2o = 0.0f;
        for (int d = 0; d < GHD; d++)
            w2o = fmaf(Wg2[n * GHD + d], Wout[d], w2o);
        float gwv = g2[n] * w2o;
        g_gw[n] = gwv;
        sr1[n] = gwv;
        sr2[n] = b2[n] * w2o;
        __syncthreads();
        if (n == 0) {
            float k1 = 0.0f, k2 = 0.0f;
            for (int i = 0; i < GHD; i++) { k1 += sr1[i]; k2 += sr2[i]; }
            g_K[0] = k1;
            g_K[1] = k2;
        }
    }
}

// ===========================================================================
// K1: h1 = relu(x @ W1 + b1); also resets g_flag (stream-ordered before mega)
// ===========================================================================
__global__ void k_enc1(const float* __restrict__ x,
                       const float* __restrict__ W1,
                       const float* __restrict__ b1) {
    const int b = blockIdx.x;
    const int j = threadIdx.x;
    if (j < 32) g_flag[b * 32 + j] = 0;    // 64 blocks x 32 = 2048 flags
    __shared__ float sx[ENC_IN];
    if (j < ENC_IN) sx[j] = x[b * ENC_IN + j];
    __syncthreads();
    float acc = b1[j];
#pragma unroll
    for (int k = 0; k < ENC_IN; k++)
        acc = fmaf(sx[k], W1[k * ENC_HID + j], acc);
    g_h1[b * ENC_HID + j] = fmaxf(acc, 0.0f);
}

// ===========================================================================
// K_MEGA: one launch, two roles by blockIdx.x.
//  [0, 2048):   enc role — enc(:, node bx, :) = h1 @ W2[:, bx*128..] + b2,
//               then set g_flag[bx].
//  [2048, 3136): gcn role — wait on the ~130 node flags of its tile, then
//               fused GCN layer-1 GEMM + collapsed layer-2 + projection.
// ===========================================================================
// enc-role smem offsets
#define ESB       528
#define EBB       272
#define E_AHI     0
#define E_ALO     33792
#define E_BHI     67584
#define E_BLO     76288
// gcn-role smem offsets
#define GSB       272
#define G_AHI     0
#define G_ALO     34816
#define G_RB      69632                    // B-half hi staging / C tile
#define G_RLO     87040                    // B-half lo staging
#define G_SMEM    104448

__global__ __launch_bounds__(256, 2) void k_mega(const float* __restrict__ W2,
                                                 const float* __restrict__ b2,
                                                 const float* __restrict__ Ah,
                                                 const float* __restrict__ g1,
                                                 const float* __restrict__ bb1,
                                                 const float* __restrict__ Wout,
                                                 const float* __restrict__ bout,
                                                 float* __restrict__ proj) {
    const int tid = threadIdx.x;
    const int L   = tid & 31;
    const int w   = tid >> 5;
    const u32 sb  = smem_u32(dynsm);

    if (blockIdx.x < N_ENC_BLK) {
        // ================= enc role =================
        const int j0 = blockIdx.x * 128;

        // ---- stage A = h1 (bf16 hi/lo), full K=256 ----
        for (int i = tid; i < 4096; i += 256) {
            int row = i >> 6, c4 = i & 63;
            float4 v = *(const float4*)&g_h1[row * ENC_HID + c4 * 4];
            u32 h0, l0, h1, l1;
            split2(v.x, v.y, h0, l0);
            split2(v.z, v.w, h1, l1);
            *(uint2*)(dynsm + E_AHI + row * ESB + c4 * 8) = make_uint2(h0, h1);
            *(uint2*)(dynsm + E_ALO + row * ESB + c4 * 8) = make_uint2(l0, l1);
        }

        const int mw = w & 1, nw = w >> 1;
        const int R0 = mw * 32, N0 = nw * 32;
        const u32 arow = (u32)(L & 15);
        const u32 kcol = (u32)((L >> 4) << 3);
        const u32 brow = (u32)((L & 7) + ((L >> 3) & 1) * 8);
        const u32 bcol = (u32)((L >> 4) << 3);

        float acc[2][4][4];
#pragma unroll
        for (int mt = 0; mt < 2; mt++)
#pragma unroll
            for (int j = 0; j < 4; j++)
#pragma unroll
                for (int c = 0; c < 4; c++) acc[mt][j][c] = 0.0f;

        float4 pf[4];
#pragma unroll
        for (int t = 0; t < 4; t++) {
            int i = tid + t * 256;
            int row = i >> 5, c4 = i & 31;
            pf[t] = *(const float4*)&W2[(size_t)row * JTOT + j0 + c4 * 4];
        }

        for (int kp = 0; kp < 8; kp++) {
            __syncthreads();
#pragma unroll
            for (int t = 0; t < 4; t++) {
                int i = tid + t * 256;
                int row = i >> 5, c4 = i & 31;
                u32 h0, l0, h1, l1;
                split2(pf[t].x, pf[t].y, h0, l0);
                split2(pf[t].z, pf[t].w, h1, l1);
                *(uint2*)(dynsm + E_BHI + row * EBB + c4 * 8) = make_uint2(h0, h1);
                *(uint2*)(dynsm + E_BLO + row * EBB + c4 * 8) = make_uint2(l0, l1);
            }
            __syncthreads();
            if (kp < 7) {
#pragma unroll
                for (int t = 0; t < 4; t++) {
                    int i = tid + t * 256;
                    int row = i >> 5, c4 = i & 31;
                    pf[t] = *(const float4*)&W2[(size_t)((kp + 1) * 32 + row) * JTOT +
                                                j0 + c4 * 4];
                }
            }

#pragma unroll
            for (int p = 0; p < 3; p++) {
                const u32 aOff = (p < 2) ? E_AHI : E_ALO;
                const u32 bOff = (p == 1) ? E_BLO : E_BHI;
#pragma unroll
                for (int ks = 0; ks < 2; ks++) {
                    u32 a0[4], a1[4];
                    u32 ka = (u32)((kp * 32 + ks * 16 + kcol) * 2);
                    ldsm4(a0, sb + aOff + (R0 + arow) * ESB + ka);
                    ldsm4(a1, sb + aOff + (R0 + 16 + arow) * ESB + ka);
                    u32 bf[2][4];
                    u32 kb = (u32)((ks * 16 + brow) * EBB);
#pragma unroll
                    for (int nt = 0; nt < 2; nt++)
                        ldsm4t(bf[nt], sb + bOff + kb + (N0 + nt * 16 + bcol) * 2);
#pragma unroll
                    for (int j = 0; j < 4; j++) {
                        u32 b0 = bf[j >> 1][(j & 1) * 2];
                        u32 b1 = bf[j >> 1][(j & 1) * 2 + 1];
                        mma16816(acc[0][j], a0, b0, b1);
                        mma16816(acc[1][j], a1, b0, b1);
                    }
                }
            }
        }

#pragma unroll
        for (int mt = 0; mt < 2; mt++) {
            int m = R0 + mt * 16 + (L >> 2);
#pragma unroll
            for (int j = 0; j < 4; j++) {
                int n = j0 + N0 + j * 8 + (L & 3) * 2;
                float b20 = __ldg(&b2[n]), b21 = __ldg(&b2[n + 1]);
                *(float2*)&g_buf0[(size_t)m * JTOT + n] =
                    make_float2(acc[mt][j][0] + b20, acc[mt][j][1] + b21);
                *(float2*)&g_buf0[(size_t)(m + 8) * JTOT + n] =
                    make_float2(acc[mt][j][2] + b20, acc[mt][j][3] + b21);
            }
        }

        // ---- publish: node blockIdx.x is complete ----
        __threadfence();
        __syncthreads();
        if (tid == 0) ((volatile int*)g_flag)[blockIdx.x] = 1;
        return;
    }

    // ================= gcn role =================
    __shared__ float sAp[128], sAn[128];
    __shared__ float sG1[128], sB1[128], sWo[128], sGw[128];
    __shared__ float sP[128][4];
    __shared__ float sT[128], sU[128];

    const int bx = blockIdx.x - N_ENC_BLK;
    const int nt = bx >> 6;                // 0..16
    const int b  = bx & 63;
    const int n0 = nt * 124;               // staged row r <-> gi = n0 - 2 + r

    if (tid < 128) {
        sG1[tid] = g1[tid];
        sB1[tid] = bb1[tid];
        sWo[tid] = Wout[tid];
        sGw[tid] = g_gw[tid];
        int gi = n0 - 2 + tid;
        sAp[tid] = (gi >= 1 && gi < NNODES) ? Ah[(size_t)gi * NNODES + gi - 1] : 0.0f;
        sAn[tid] = (gi >= 0 && gi < NNODES - 1) ? Ah[(size_t)gi * NNODES + gi + 1] : 0.0f;
    }

    // ---- stage B half 0 (no dependency on enc output) ----
    {
        uint4* dh = (uint4*)(dynsm + G_RB);
        uint4* dl = (uint4*)(dynsm + G_RLO);
        for (int i = tid; i < 1088; i += 256) {
            dh[i] = ((const uint4*)g_BH)[i];
            dl[i] = ((const uint4*)g_BL)[i];
        }
    }

    // ---- wait for the nodes this tile reads ----
    if (tid < 128) {
        int gi = min(NNODES - 1, max(0, n0 - 2 + tid));
        while (((volatile int*)g_flag)[gi] == 0) __nanosleep(64);
    }
    __threadfence();
    __syncthreads();

    // ---- LN1 + bf16 split -> A tiles (warp w owns rows {w+8t}) ----
    const int c0 = 2 * L, c2 = 64 + 2 * L;
#pragma unroll 4
    for (int t = 0; t < 16; t++) {
        int row = w + 8 * t;
        int gi  = min(NNODES - 1, max(0, n0 - 2 + row));
        const float* p = &g_buf0[((size_t)b * NNODES + gi) * GHD + c0];
        float2 v0 = *(const float2*)p;
        float2 v1 = *(const float2*)(p + 64);
        float s = v0.x + v0.y + v1.x + v1.y;
        float q = v0.x * v0.x + v0.y * v0.y + v1.x * v1.x + v1.y * v1.y;
#pragma unroll
        for (int o = 16; o; o >>= 1) {
            s += __shfl_xor_sync(0xFFFFFFFFu, s, o);
            q += __shfl_xor_sync(0xFFFFFFFFu, q, o);
        }
        float mu   = s * (1.0f / GHD);
        float rstd = rsqrtf(fmaxf(q * (1.0f / GHD) - mu * mu, 0.0f) + LN_EPS);
        float f0 = (v0.x - mu) * rstd * sG1[c0] + sB1[c0];
        float f1 = (v0.y - mu) * rstd * sG1[c0 + 1] + sB1[c0 + 1];
        float f2 = (v1.x - mu) * rstd * sG1[c2] + sB1[c2];
        float f3 = (v1.y - mu) * rstd * sG1[c2 + 1] + sB1[c2 + 1];
        u32 h0, l0, h1, l1;
        split2(f0, f1, h0, l0);
        split2(f2, f3, h1, l1);
        *(u32*)(dynsm + G_AHI + row * GSB + L * 4)       = h0;
        *(u32*)(dynsm + G_AHI + row * GSB + 128 + L * 4) = h1;
        *(u32*)(dynsm + G_ALO + row * GSB + L * 4)       = l0;
        *(u32*)(dynsm + G_ALO + row * GSB + 128 + L * 4) = l1;
    }
    __syncthreads();

    const int mw = w & 3, nh = w >> 2;
    const int R0 = mw * 32, N0 = nh * 32;
    const u32 arow = (u32)(L & 15);
    const u32 kcol = (u32)((L >> 4) << 3);
    float* sC = (float*)(dynsm + G_RB);
    const float K1 = g_K[0], K2 = g_K[1];

    for (int h = 0; h < 2; h++) {
        if (h) {
            uint4* dh = (uint4*)(dynsm + G_RB);
            uint4* dl = (uint4*)(dynsm + G_RLO);
            for (int i = tid; i < 1088; i += 256) {
                dh[i] = ((const uint4*)g_BH)[1088 + i];
                dl[i] = ((const uint4*)g_BL)[1088 + i];
            }
            __syncthreads();
        }

        // ---- MMA: 128M x 64N, 3-pass bf16 split (warp tile 32x32) ----
        float acc[2][4][4];
#pragma unroll
        for (int mt = 0; mt < 2; mt++)
#pragma unroll
            for (int j = 0; j < 4; j++)
#pragma unroll
                for (int c = 0; c < 4; c++) acc[mt][j][c] = 0.0f;

#pragma unroll
        for (int p = 0; p < 3; p++) {
            const u32 aOff = (p < 2) ? G_AHI : G_ALO;
            const u32 bOff = (p == 1) ? (u32)G_RLO : (u32)G_RB;
#pragma unroll
            for (int ks = 0; ks < 8; ks++) {
                u32 kb = (u32)((ks * 16 + kcol) * 2);
                u32 a0[4], a1[4];
                ldsm4(a0, sb + aOff + (R0 + arow) * GSB + kb);
                ldsm4(a1, sb + aOff + (R0 + 16 + arow) * GSB + kb);
                u32 bf[2][4];
#pragma unroll
                for (int nth = 0; nth < 2; nth++)
                    ldsm4(bf[nth], sb + bOff + (N0 + nth * 16 + arow) * GSB + kb);
#pragma unroll
                for (int j = 0; j < 4; j++) {
                    u32 b0 = bf[j >> 1][(j & 1)];
                    u32 b1 = bf[j >> 1][(j & 1) + 2];
                    mma16816(acc[0][j], a0, b0, b1);
                    mma16816(acc[1][j], a1, b0, b1);
                }
            }
        }
        __syncthreads();

        // ---- C frags -> sC ----
#pragma unroll
        for (int mt = 0; mt < 2; mt++) {
            int m = R0 + mt * 16 + (L >> 2);
#pragma unroll
            for (int j = 0; j < 4; j++) {
                int n = N0 + j * 8 + (L & 3) * 2;
                *(float2*)&sC[m * 68 + n] =
                    make_float2(acc[mt][j][0], acc[mt][j][1]);
                *(float2*)&sC[(m + 8) * 68 + n] =
                    make_float2(acc[mt][j][2], acc[mt][j][3]);
            }
        }
        __syncthreads();

        // ---- dot pass: out1 cols of this half -> 4 partial dots per row ----
        const int cg = h * 64 + 2 * L;
#pragma unroll 2
        for (int t = 0; t < 16; t++) {
            int row = w + 8 * t;
            if (row < 1 || row > 126) continue;
            int gi = min(NNODES - 1, max(0, n0 - 2 + row));
            float2 iv = *(const float2*)&g_buf0[((size_t)b * NNODES + gi) * GHD + cg];
            float2 wp = *(const float2*)&sC[(row - 1) * 68 + 2 * L];
            float2 wn = *(const float2*)&sC[(row + 1) * 68 + 2 * L];
            float ap = sAp[row], an = sAn[row];
            float o0 = fmaf(an, wn.x, fmaf(ap, wp.x, iv.x));
            float o1 = fmaf(an, wn.y, fmaf(ap, wp.y, iv.y));
            float sv = o0 + o1;
            float sq = o0 * o0 + o1 * o1;
            float st = o0 * sWo[cg] + o1 * sWo[cg + 1];
            float sg = o0 * sGw[cg] + o1 * sGw[cg + 1];
#pragma unroll
            for (int o = 16; o; o >>= 1) {
                sv += __shfl_xor_sync(0xFFFFFFFFu, sv, o);
                sq += __shfl_xor_sync(0xFFFFFFFFu, sq, o);
                st += __shfl_xor_sync(0xFFFFFFFFu, st, o);
                sg += __shfl_xor_sync(0xFFFFFFFFu, sg, o);
            }
            if (L == 0) {
                if (h == 0) {
                    sP[row][0] = sv; sP[row][1] = sq;
                    sP[row][2] = st; sP[row][3] = sg;
                } else {
                    sv += sP[row][0];
                    sq += sP[row][1];
                    st += sP[row][2];
                    sg += sP[row][3];
                    float mu   = sv * (1.0f / GHD);
                    float rstd = rsqrtf(fmaxf(sq * (1.0f / GHD) - mu * mu, 0.0f) +
                                        LN_EPS);
                    sT[row] = st;
                    sU[row] = rstd * (sg - mu * K1) + K2;
                }
            }
        }
        __syncthreads();
    }

    // ---- final: rows 2..125 -> proj ----
    if (tid < 124) {
        int row = tid + 2;
        int gi  = n0 + tid;
        if (gi < NNODES) {
            float f = sT[row] + sAp[row] * sU[row - 1] + sAn[row] * sU[row + 1] +
                      bout[0];
            proj[b * NNODES + gi] = f;
        }
    }
}

// ===========================================================================
extern "C" void kernel_launch(void* const* d_in, const int* in_sizes, int n_in,
                              void* d_out, int out_size) {
    const float* x    = (const float*)d_in[0];
    const float* Ah   = (const float*)d_in[1];
    const float* W1   = (const float*)d_in[2];
    const float* b1   = (const float*)d_in[3];
    const float* W2   = (const float*)d_in[4];
    const float* b2   = (const float*)d_in[5];
    const float* Wg1  = (const float*)d_in[6];
    const float* Wg2  = (const float*)d_in[7];
    const float* g1   = (const float*)d_in[8];
    const float* bb1  = (const float*)d_in[9];
    const float* g2   = (const float*)d_in[10];
    const float* bb2  = (const float*)d_in[11];
    const float* Wout = (const float*)d_in[12];
    const float* bout = (const float*)d_in[13];
    float* out = (float*)d_out;

    cudaFuncSetAttribute(k_mega, cudaFuncAttributeMaxDynamicSharedMemorySize,
                         G_SMEM);

    k_prep<<<2, GHD>>>(Wg1, Wg2, Wout, g2, bb2);
    k_enc1<<<BSZ, ENC_HID>>>(x, W1, b1);
    k_mega<<<N_ENC_BLK + N_GCN_BLK, 256, G_SMEM>>>(W2, b2, Ah, g1, bb1,
                                                   Wout, bout, out);
}